// round 2
// baseline (speedup 1.0000x reference)
#include <cuda_runtime.h>
#include <cstdint>

#define B_SZ   4096
#define D_SZ   512
#define MARGIN 0.5f
#define EPSV   1e-6f
#define BIGV   1e9f

#define BM 64
#define BN 64
#define BK 32
#define JSPLIT 4
#define COLS_PER_SPLIT (B_SZ / JSPLIT)   // 1024
#define NTHREADS 256
#define SPAD 4                            // smem pad (keeps float4 alignment)

// scratch (no cudaMalloc allowed)
__device__ float g_sq[B_SZ];
__device__ float g_s[B_SZ];
__device__ float g_hp[JSPLIT][B_SZ];
__device__ float g_hn[JSPLIT][B_SZ];

// ---------------------------------------------------------------------------
// Kernel 1: per-row sum and sum-of-squares. One warp per row.
// ---------------------------------------------------------------------------
__global__ void stats_kernel(const float* __restrict__ E) {
    int warp = (blockIdx.x * blockDim.x + threadIdx.x) >> 5;
    int lane = threadIdx.x & 31;
    if (warp >= B_SZ) return;
    const float4* row = reinterpret_cast<const float4*>(E + (size_t)warp * D_SZ);
    float s = 0.f, sq = 0.f;
#pragma unroll
    for (int q = 0; q < 4; q++) {
        float4 v = row[lane + 32 * q];
        s  += v.x + v.y + v.z + v.w;
        sq += v.x * v.x + v.y * v.y + v.z * v.z + v.w * v.w;
    }
#pragma unroll
    for (int off = 16; off > 0; off >>= 1) {
        s  += __shfl_xor_sync(0xffffffffu, s,  off);
        sq += __shfl_xor_sync(0xffffffffu, sq, off);
    }
    if (lane == 0) { g_s[warp] = s; g_sq[warp] = sq; }
}

// ---------------------------------------------------------------------------
// Kernel 2: fused gram-tile + distance + hardest pos/neg (per column split).
// grid = (B/BM, JSPLIT), block = 256 threads, 4x4 micro-tile per thread.
// Labels are int32 (JAX x64-disabled downgrades jnp.int64 -> int32).
// ---------------------------------------------------------------------------
__global__ __launch_bounds__(NTHREADS, 2)
void triplet_tile_kernel(const float* __restrict__ E,
                         const int* __restrict__ lab) {
    __shared__ float As[BK][BM + SPAD];
    __shared__ float Bs[BK][BN + SPAD];
    __shared__ float sqi[BM], si[BM];
    __shared__ float sqj[BN], sj[BN];
    __shared__ int   labi[BM], labj[BN];

    const int tid = threadIdx.x;
    const int tx  = tid & 15;        // column group
    const int ty  = tid >> 4;        // row group
    const int i0  = blockIdx.x * BM;
    const int split = blockIdx.y;
    const int jbase = split * COLS_PER_SPLIT;

    const int lrow = tid >> 3;       // 0..31
    const int lk4  = tid & 7;        // 0..7 (float4 index within BK)

    if (tid < BM) {
        sqi[tid]  = g_sq[i0 + tid];
        si[tid]   = g_s[i0 + tid];
        labi[tid] = lab[i0 + tid];
    }

    float hp[4], hn[4];
#pragma unroll
    for (int r = 0; r < 4; r++) { hp[r] = -BIGV; hn[r] = BIGV; }

    for (int jt = 0; jt < COLS_PER_SPLIT; jt += BN) {
        const int j0 = jbase + jt;
        __syncthreads();   // protect labj/sqj/sj reuse from previous tile epilogue
        if (tid < BN) {
            sqj[tid]  = g_sq[j0 + tid];
            sj[tid]   = g_s[j0 + tid];
            labj[tid] = lab[j0 + tid];
        }

        float acc[4][4];
#pragma unroll
        for (int r = 0; r < 4; r++)
#pragma unroll
            for (int c = 0; c < 4; c++) acc[r][c] = 0.f;

        for (int kc = 0; kc < D_SZ; kc += BK) {
            __syncthreads();
#pragma unroll
            for (int half = 0; half < 2; half++) {
                int r = lrow + half * 32;
                float4 va = *reinterpret_cast<const float4*>(
                    &E[(size_t)(i0 + r) * D_SZ + kc + lk4 * 4]);
                As[lk4 * 4 + 0][r] = va.x;
                As[lk4 * 4 + 1][r] = va.y;
                As[lk4 * 4 + 2][r] = va.z;
                As[lk4 * 4 + 3][r] = va.w;
                float4 vb = *reinterpret_cast<const float4*>(
                    &E[(size_t)(j0 + r) * D_SZ + kc + lk4 * 4]);
                Bs[lk4 * 4 + 0][r] = vb.x;
                Bs[lk4 * 4 + 1][r] = vb.y;
                Bs[lk4 * 4 + 2][r] = vb.z;
                Bs[lk4 * 4 + 3][r] = vb.w;
            }
            __syncthreads();
#pragma unroll 8
            for (int k = 0; k < BK; k++) {
                float4 a = *reinterpret_cast<const float4*>(&As[k][ty * 4]);
                float4 b = *reinterpret_cast<const float4*>(&Bs[k][tx * 4]);
                acc[0][0] += a.x * b.x; acc[0][1] += a.x * b.y;
                acc[0][2] += a.x * b.z; acc[0][3] += a.x * b.w;
                acc[1][0] += a.y * b.x; acc[1][1] += a.y * b.y;
                acc[1][2] += a.y * b.z; acc[1][3] += a.y * b.w;
                acc[2][0] += a.z * b.x; acc[2][1] += a.z * b.y;
                acc[2][2] += a.z * b.z; acc[2][3] += a.z * b.w;
                acc[3][0] += a.w * b.x; acc[3][1] += a.w * b.y;
                acc[3][2] += a.w * b.z; acc[3][3] += a.w * b.w;
            }
        }

        // epilogue: distances + masking
#pragma unroll
        for (int r = 0; r < 4; r++) {
            const int ir = ty * 4 + r;
            const int gi = i0 + ir;
            const float sqr = sqi[ir];
            const float sr  = si[ir];
            const int   lr  = labi[ir];
#pragma unroll
            for (int c = 0; c < 4; c++) {
                const int jc = tx * 4 + c;
                const int gj = j0 + jc;
                float d2 = sqr + sqj[jc] - 2.f * acc[r][c]
                         + 2.f * EPSV * (sr - sj[jc])
                         + (float)D_SZ * EPSV * EPSV;
                float dv = sqrtf(fmaxf(d2, 0.f));
                bool same = (lr == labj[jc]);
                if (same) {
                    if (gi != gj) hp[r] = fmaxf(hp[r], dv);
                } else {
                    hn[r] = fminf(hn[r], dv);
                }
            }
        }
    }

    // reduce across the 16 tx lanes sharing each row group (within half-warps)
#pragma unroll
    for (int off = 1; off < 16; off <<= 1) {
#pragma unroll
        for (int r = 0; r < 4; r++) {
            hp[r] = fmaxf(hp[r], __shfl_xor_sync(0xffffffffu, hp[r], off));
            hn[r] = fminf(hn[r], __shfl_xor_sync(0xffffffffu, hn[r], off));
        }
    }
    if (tx == 0) {
#pragma unroll
        for (int r = 0; r < 4; r++) {
            int gi = i0 + ty * 4 + r;
            g_hp[split][gi] = hp[r];
            g_hn[split][gi] = hn[r];
        }
    }
}

// ---------------------------------------------------------------------------
// Kernel 3: combine splits, validity, mean.
// ---------------------------------------------------------------------------
__global__ void finalize_kernel(float* __restrict__ out) {
    __shared__ float ssum[NTHREADS];
    __shared__ float scnt[NTHREADS];
    const int tid = threadIdx.x;
    float sum = 0.f, cnt = 0.f;
    for (int i = tid; i < B_SZ; i += NTHREADS) {
        float hp = -BIGV, hn = BIGV;
#pragma unroll
        for (int s = 0; s < JSPLIT; s++) {
            hp = fmaxf(hp, g_hp[s][i]);
            hn = fminf(hn, g_hn[s][i]);
        }
        bool valid = (hp > -0.5f * BIGV) && (hn < 0.5f * BIGV);
        if (valid) {
            float v = hp - hn + MARGIN;
            sum += (v > 0.f) ? v : 0.f;
            cnt += 1.f;
        }
    }
    ssum[tid] = sum; scnt[tid] = cnt;
    __syncthreads();
    for (int off = NTHREADS / 2; off > 0; off >>= 1) {
        if (tid < off) {
            ssum[tid] += ssum[tid + off];
            scnt[tid] += scnt[tid + off];
        }
        __syncthreads();
    }
    if (tid == 0) {
        float c = scnt[0];
        out[0] = (c > 0.f) ? (ssum[0] / c) : 0.f;
    }
}

// ---------------------------------------------------------------------------
extern "C" void kernel_launch(void* const* d_in, const int* in_sizes, int n_in,
                              void* d_out, int out_size) {
    const float* E   = (const float*)d_in[0];
    const int*   lab = (const int*)d_in[1];
    float*       out = (float*)d_out;
    (void)in_sizes; (void)n_in; (void)out_size;

    // one warp per row: 4096 warps -> 512 blocks of 256 threads
    stats_kernel<<<B_SZ / 8, 256>>>(E);
    dim3 grid(B_SZ / BM, JSPLIT);
    triplet_tile_kernel<<<grid, NTHREADS>>>(E, lab);
    finalize_kernel<<<1, NTHREADS>>>(out);
}

// round 4
// speedup vs baseline: 6.5314x; 6.5314x over previous
#include <cuda_runtime.h>
#include <cuda_fp16.h>
#include <cstdint>

#define B_SZ   4096
#define D_SZ   512
#define MARGIN 0.5f
#define EPSV   1e-6f
#define BIGV   1e9f

#define NSPLIT (B_SZ / 128)       // 32 j-tiles
#define STG    32768              // bytes per pipeline stage (A 16K + B 16K)
#define DYN_SMEM (3 * STG)

// ---------------- device scratch (no cudaMalloc allowed) ----------------
__device__ __half Ehalf[B_SZ * D_SZ];
__device__ float  g_q[B_SZ];   // sq - 2*eps*s
__device__ float  g_p[B_SZ];   // sq + 2*eps*s + D*eps^2
__device__ float  g_hp[NSPLIT][B_SZ];
__device__ float  g_hn[NSPLIT][B_SZ];

// ---------------- helpers ----------------
__device__ __forceinline__ uint32_t smem_u32(const void* p) {
    uint32_t a;
    asm("{ .reg .u64 t; cvta.to.shared.u64 t, %1; cvt.u32.u64 %0, t; }" : "=r"(a) : "l"(p));
    return a;
}

#define LDMATRIX_X4(r, addr)                                                      \
    asm volatile("ldmatrix.sync.aligned.m8n8.x4.shared.b16 {%0,%1,%2,%3}, [%4];"  \
        : "=r"((r)[0]), "=r"((r)[1]), "=r"((r)[2]), "=r"((r)[3]) : "r"(addr))

#define MMA16816(D, A, b0, b1)                                                    \
    asm volatile("mma.sync.aligned.m16n8k16.row.col.f32.f16.f16.f32 "             \
        "{%0,%1,%2,%3}, {%4,%5,%6,%7}, {%8,%9}, {%0,%1,%2,%3};"                   \
        : "+f"((D)[0]), "+f"((D)[1]), "+f"((D)[2]), "+f"((D)[3])                  \
        : "r"((A)[0]), "r"((A)[1]), "r"((A)[2]), "r"((A)[3]), "r"(b0), "r"(b1))

#define CP_ASYNC16(dst, src)                                                      \
    asm volatile("cp.async.cg.shared.global [%0], [%1], 16;"                      \
        :: "r"(dst), "l"(src) : "memory")
#define CP_COMMIT() asm volatile("cp.async.commit_group;" ::: "memory")

// load one 128x64-fp16 A tile + B tile into a stage (SW128-style xor swizzle)
__device__ __forceinline__ void load_stage(uint32_t base, int i0, int j0,
                                           int kc, int tid) {
    uint32_t As = base, Bs = base + 16384;
#pragma unroll
    for (int it = 0; it < 4; it++) {
        int idx = tid + it * 256;
        int r = idx >> 3, ch = idx & 7;
        uint32_t dst = As + r * 128 + ((ch ^ (r & 7)) << 4);
        const void* src = &Ehalf[(size_t)(i0 + r) * D_SZ + kc + ch * 8];
        CP_ASYNC16(dst, src);
    }
#pragma unroll
    for (int it = 0; it < 4; it++) {
        int idx = tid + it * 256;
        int r = idx >> 3, ch = idx & 7;
        uint32_t dst = Bs + r * 128 + ((ch ^ (r & 7)) << 4);
        const void* src = &Ehalf[(size_t)(j0 + r) * D_SZ + kc + ch * 8];
        CP_ASYNC16(dst, src);
    }
}

// ---------------------------------------------------------------------------
// Kernel 0: fp32 -> fp16 convert
// ---------------------------------------------------------------------------
__global__ void prep_kernel(const float* __restrict__ E) {
    int idx = blockIdx.x * blockDim.x + threadIdx.x;
    float2 v = reinterpret_cast<const float2*>(E)[idx];
    reinterpret_cast<__half2*>(Ehalf)[idx] = __floats2half2_rn(v.x, v.y);
}

// ---------------------------------------------------------------------------
// Kernel 1: per-row stats (fp32 exact)
// ---------------------------------------------------------------------------
__global__ void stats_kernel(const float* __restrict__ E) {
    int warp = (blockIdx.x * blockDim.x + threadIdx.x) >> 5;
    int lane = threadIdx.x & 31;
    if (warp >= B_SZ) return;
    const float4* row = reinterpret_cast<const float4*>(E + (size_t)warp * D_SZ);
    float s = 0.f, sq = 0.f;
#pragma unroll
    for (int q = 0; q < 4; q++) {
        float4 v = row[lane + 32 * q];
        s  += v.x + v.y + v.z + v.w;
        sq += v.x * v.x + v.y * v.y + v.z * v.z + v.w * v.w;
    }
#pragma unroll
    for (int off = 16; off > 0; off >>= 1) {
        s  += __shfl_xor_sync(0xffffffffu, s,  off);
        sq += __shfl_xor_sync(0xffffffffu, sq, off);
    }
    if (lane == 0) {
        g_q[warp] = sq - 2.f * EPSV * s;
        g_p[warp] = sq + 2.f * EPSV * s + (float)D_SZ * EPSV * EPSV;
    }
}

// ---------------------------------------------------------------------------
// Kernel 2: 128x128x512 fp16 mma.sync gram tile + fused hardest pos/neg
// ---------------------------------------------------------------------------
__global__ void __launch_bounds__(256, 2)
gemm_triplet_kernel(const int* __restrict__ lab) {
    extern __shared__ __align__(1024) char dsm[];
    __shared__ int   s_labi[128];
    __shared__ int   s_labj[128];
    __shared__ float s_qj[128];
    __shared__ float hp_s[128][4];
    __shared__ float hn_s[128][4];

    const int tid  = threadIdx.x;
    const int wid  = tid >> 5, lane = tid & 31;
    const int wr   = wid >> 2, wc = wid & 3;        // 2 x 4 warp grid
    const int i0   = blockIdx.x * 128;
    const int j0   = blockIdx.y * 128;
    const uint32_t smem = smem_u32(dsm);

    if (tid < 128) {
        s_labi[tid] = lab[i0 + tid];
        s_labj[tid] = lab[j0 + tid];
        s_qj[tid]   = g_q[j0 + tid];
    }

    float d[4][4][4];
#pragma unroll
    for (int a = 0; a < 4; a++)
#pragma unroll
        for (int b = 0; b < 4; b++)
#pragma unroll
            for (int e = 0; e < 4; e++) d[a][b][e] = 0.f;

    // prologue: chunks 0,1
    load_stage(smem + 0 * STG, i0, j0, 0,  tid); CP_COMMIT();
    load_stage(smem + 1 * STG, i0, j0, 64, tid); CP_COMMIT();

#pragma unroll 1
    for (int c = 0; c < 8; c++) {
        if (c >= 6) asm volatile("cp.async.wait_group 0;" ::: "memory");
        else        asm volatile("cp.async.wait_group 1;" ::: "memory");
        __syncthreads();
        if (c + 2 < 8) {
            load_stage(smem + ((c + 2) % 3) * STG, i0, j0, (c + 2) * 64, tid);
            CP_COMMIT();
        }
        const uint32_t As = smem + (c % 3) * STG;
        const uint32_t Bs = As + 16384;
#pragma unroll
        for (int ks = 0; ks < 4; ks++) {
            uint32_t a[4][4];
#pragma unroll
            for (int mt = 0; mt < 4; mt++) {
                int arow = wr * 64 + mt * 16 + (lane & 15);
                uint32_t ad = As + arow * 128 +
                              ((((ks << 1) | (lane >> 4)) ^ (arow & 7)) << 4);
                LDMATRIX_X4(a[mt], ad);
            }
#pragma unroll
            for (int np = 0; np < 2; np++) {
                int brow = wc * 32 + np * 16 + (lane & 15);
                uint32_t bd = Bs + brow * 128 +
                              ((((ks << 1) | (lane >> 4)) ^ (brow & 7)) << 4);
                uint32_t b[4];
                LDMATRIX_X4(b, bd);
#pragma unroll
                for (int mt = 0; mt < 4; mt++) {
                    MMA16816(d[mt][2 * np],     a[mt], b[0], b[2]);
                    MMA16816(d[mt][2 * np + 1], a[mt], b[1], b[3]);
                }
            }
        }
    }

    // epilogue: m = q_j - 2*gram; masked hardest pos/neg per row
#pragma unroll
    for (int mt = 0; mt < 4; mt++) {
        int r0 = wr * 64 + mt * 16 + (lane >> 2);
        int li0 = s_labi[r0], li1 = s_labi[r0 + 8];
        float hp0 = -BIGV, hp1 = -BIGV, hn0 = BIGV, hn1 = BIGV;
#pragma unroll
        for (int nt = 0; nt < 4; nt++) {
            int c0 = wc * 32 + nt * 8 + ((lane & 3) << 1);
            float q0 = s_qj[c0], q1 = s_qj[c0 + 1];
            int lj0 = s_labj[c0], lj1 = s_labj[c0 + 1];
            float m00 = fmaf(d[mt][nt][0], -2.f, q0);
            float m01 = fmaf(d[mt][nt][1], -2.f, q1);
            float m10 = fmaf(d[mt][nt][2], -2.f, q0);
            float m11 = fmaf(d[mt][nt][3], -2.f, q1);
            if (li0 == lj0) hp0 = fmaxf(hp0, m00); else hn0 = fminf(hn0, m00);
            if (li0 == lj1) hp0 = fmaxf(hp0, m01); else hn0 = fminf(hn0, m01);
            if (li1 == lj0) hp1 = fmaxf(hp1, m10); else hn1 = fminf(hn1, m10);
            if (li1 == lj1) hp1 = fmaxf(hp1, m11); else hn1 = fminf(hn1, m11);
        }
#pragma unroll
        for (int off = 1; off < 4; off <<= 1) {
            hp0 = fmaxf(hp0, __shfl_xor_sync(0xffffffffu, hp0, off));
            hp1 = fmaxf(hp1, __shfl_xor_sync(0xffffffffu, hp1, off));
            hn0 = fminf(hn0, __shfl_xor_sync(0xffffffffu, hn0, off));
            hn1 = fminf(hn1, __shfl_xor_sync(0xffffffffu, hn1, off));
        }
        if ((lane & 3) == 0) {
            hp_s[r0][wc] = hp0; hp_s[r0 + 8][wc] = hp1;
            hn_s[r0][wc] = hn0; hn_s[r0 + 8][wc] = hn1;
        }
    }
    __syncthreads();
    if (tid < 128) {
        float hp = fmaxf(fmaxf(hp_s[tid][0], hp_s[tid][1]),
                         fmaxf(hp_s[tid][2], hp_s[tid][3]));
        float hn = fminf(fminf(hn_s[tid][0], hn_s[tid][1]),
                         fminf(hn_s[tid][2], hn_s[tid][3]));
        g_hp[blockIdx.y][i0 + tid] = hp;
        g_hn[blockIdx.y][i0 + tid] = hn;
    }
}

// ---------------------------------------------------------------------------
// Kernel 3: histogram validity, combine splits, sqrt, mean.
// ---------------------------------------------------------------------------
__global__ void finalize_kernel(const int* __restrict__ lab, float* __restrict__ out) {
    __shared__ int   cnt[512];
    __shared__ float ssum[256], scnt[256];
    const int tid = threadIdx.x;
    for (int i = tid; i < 512; i += 256) cnt[i] = 0;
    __syncthreads();
    for (int i = tid; i < B_SZ; i += 256) atomicAdd(&cnt[lab[i]], 1);
    __syncthreads();
    float sum = 0.f, c = 0.f;
    for (int i = tid; i < B_SZ; i += 256) {
        float hp = -BIGV, hn = BIGV;
#pragma unroll
        for (int s = 0; s < NSPLIT; s++) {
            hp = fmaxf(hp, g_hp[s][i]);
            hn = fminf(hn, g_hn[s][i]);
        }
        int k = cnt[lab[i]];
        bool valid = (k >= 2) && (k < B_SZ);
        float p = g_p[i];
        float dp = sqrtf(fmaxf(p + hp, 0.f));
        float dn = sqrtf(fmaxf(p + hn, 0.f));
        float v = dp - dn + MARGIN;
        if (valid) { sum += (v > 0.f) ? v : 0.f; c += 1.f; }
    }
    ssum[tid] = sum; scnt[tid] = c;
    __syncthreads();
    for (int off = 128; off > 0; off >>= 1) {
        if (tid < off) { ssum[tid] += ssum[tid + off]; scnt[tid] += scnt[tid + off]; }
        __syncthreads();
    }
    if (tid == 0) out[0] = (scnt[0] > 0.f) ? (ssum[0] / scnt[0]) : 0.f;
}

// ---------------------------------------------------------------------------
extern "C" void kernel_launch(void* const* d_in, const int* in_sizes, int n_in,
                              void* d_out, int out_size) {
    const float* E   = (const float*)d_in[0];
    const int*   lab = (const int*)d_in[1];
    float*       out = (float*)d_out;
    (void)in_sizes; (void)n_in; (void)out_size;

    cudaFuncSetAttribute(gemm_triplet_kernel,
                         cudaFuncAttributeMaxDynamicSharedMemorySize, DYN_SMEM);

    prep_kernel<<<(B_SZ * D_SZ / 2) / 256, 256>>>(E);
    stats_kernel<<<B_SZ / 8, 256>>>(E);
    gemm_triplet_kernel<<<dim3(B_SZ / 128, B_SZ / 128), 256, DYN_SMEM>>>(lab);
    finalize_kernel<<<1, 256>>>(lab, out);
}

// round 5
// speedup vs baseline: 10.0888x; 1.5447x over previous
#include <cuda_runtime.h>
#include <cuda_fp16.h>
#include <cstdint>

#define B_SZ   4096
#define D_SZ   512
#define MARGIN 0.5f
#define EPSV   1e-6f
#define BIGV   1e9f

#define NSPLIT (B_SZ / 128)       // 32 j-tiles
#define STG    32768              // bytes per pipeline stage (A 16K + B 16K)
#define DYN_SMEM (3 * STG)
#define CBLKS  16                 // combine blocks (4096 / 256)

// ---------------- device scratch (no cudaMalloc allowed) ----------------
__device__ __half Ehalf[B_SZ * D_SZ];
__device__ float  g_q[B_SZ];   // sq - 2*eps*s
__device__ float  g_p[B_SZ];   // sq + 2*eps*s + D*eps^2
__device__ float  g_hp[NSPLIT][B_SZ];
__device__ float  g_hn[NSPLIT][B_SZ];
__device__ float  g_psum[CBLKS];
__device__ float  g_pcnt[CBLKS];

// ---------------- helpers ----------------
__device__ __forceinline__ uint32_t smem_u32(const void* p) {
    uint32_t a;
    asm("{ .reg .u64 t; cvta.to.shared.u64 t, %1; cvt.u32.u64 %0, t; }" : "=r"(a) : "l"(p));
    return a;
}

#define LDMATRIX_X4(r, addr)                                                      \
    asm volatile("ldmatrix.sync.aligned.m8n8.x4.shared.b16 {%0,%1,%2,%3}, [%4];"  \
        : "=r"((r)[0]), "=r"((r)[1]), "=r"((r)[2]), "=r"((r)[3]) : "r"(addr))

#define MMA16816(D, A, b0, b1)                                                    \
    asm volatile("mma.sync.aligned.m16n8k16.row.col.f32.f16.f16.f32 "             \
        "{%0,%1,%2,%3}, {%4,%5,%6,%7}, {%8,%9}, {%0,%1,%2,%3};"                   \
        : "+f"((D)[0]), "+f"((D)[1]), "+f"((D)[2]), "+f"((D)[3])                  \
        : "r"((A)[0]), "r"((A)[1]), "r"((A)[2]), "r"((A)[3]), "r"(b0), "r"(b1))

#define CP_ASYNC16(dst, src)                                                      \
    asm volatile("cp.async.cg.shared.global [%0], [%1], 16;"                      \
        :: "r"(dst), "l"(src) : "memory")
#define CP_COMMIT() asm volatile("cp.async.commit_group;" ::: "memory")

// load one 128x64-fp16 A tile + B tile into a stage (xor swizzle)
__device__ __forceinline__ void load_stage(uint32_t base, int i0, int j0,
                                           int kc, int tid) {
    uint32_t As = base, Bs = base + 16384;
#pragma unroll
    for (int it = 0; it < 4; it++) {
        int idx = tid + it * 256;
        int r = idx >> 3, ch = idx & 7;
        uint32_t dst = As + r * 128 + ((ch ^ (r & 7)) << 4);
        const void* src = &Ehalf[(size_t)(i0 + r) * D_SZ + kc + ch * 8];
        CP_ASYNC16(dst, src);
    }
#pragma unroll
    for (int it = 0; it < 4; it++) {
        int idx = tid + it * 256;
        int r = idx >> 3, ch = idx & 7;
        uint32_t dst = Bs + r * 128 + ((ch ^ (r & 7)) << 4);
        const void* src = &Ehalf[(size_t)(j0 + r) * D_SZ + kc + ch * 8];
        CP_ASYNC16(dst, src);
    }
}

// ---------------------------------------------------------------------------
// Kernel 1: fused fp32->fp16 convert + per-row stats. One warp per row.
// ---------------------------------------------------------------------------
__global__ void prep_stats_kernel(const float* __restrict__ E) {
    int warp = (blockIdx.x * blockDim.x + threadIdx.x) >> 5;
    int lane = threadIdx.x & 31;
    const float4* row = reinterpret_cast<const float4*>(E + (size_t)warp * D_SZ);
    uint2* hout = reinterpret_cast<uint2*>(Ehalf + (size_t)warp * D_SZ);
    float s = 0.f, sq = 0.f;
#pragma unroll
    for (int q = 0; q < 4; q++) {
        float4 v = row[lane + 32 * q];
        s  += v.x + v.y + v.z + v.w;
        sq += v.x * v.x + v.y * v.y + v.z * v.z + v.w * v.w;
        __half2 h0 = __floats2half2_rn(v.x, v.y);
        __half2 h1 = __floats2half2_rn(v.z, v.w);
        uint2 packed;
        packed.x = *reinterpret_cast<uint32_t*>(&h0);
        packed.y = *reinterpret_cast<uint32_t*>(&h1);
        hout[lane + 32 * q] = packed;
    }
#pragma unroll
    for (int off = 16; off > 0; off >>= 1) {
        s  += __shfl_xor_sync(0xffffffffu, s,  off);
        sq += __shfl_xor_sync(0xffffffffu, sq, off);
    }
    if (lane == 0) {
        g_q[warp] = sq - 2.f * EPSV * s;
        g_p[warp] = sq + 2.f * EPSV * s + (float)D_SZ * EPSV * EPSV;
    }
}

// ---------------------------------------------------------------------------
// Kernel 2: 128x128x512 fp16 mma.sync gram tile + fused hardest pos/neg
// ---------------------------------------------------------------------------
__global__ void __launch_bounds__(256, 2)
gemm_triplet_kernel(const int* __restrict__ lab) {
    extern __shared__ __align__(1024) char dsm[];
    __shared__ int   s_labi[128];
    __shared__ int   s_labj[128];
    __shared__ float s_qj[128];
    __shared__ float hp_s[128][4];
    __shared__ float hn_s[128][4];

    const int tid  = threadIdx.x;
    const int wid  = tid >> 5, lane = tid & 31;
    const int wr   = wid >> 2, wc = wid & 3;        // 2 x 4 warp grid
    const int i0   = blockIdx.x * 128;
    const int j0   = blockIdx.y * 128;
    const uint32_t smem = smem_u32(dsm);

    if (tid < 128) {
        s_labi[tid] = lab[i0 + tid];
        s_labj[tid] = lab[j0 + tid];
        s_qj[tid]   = g_q[j0 + tid];
    }

    float d[4][4][4];
#pragma unroll
    for (int a = 0; a < 4; a++)
#pragma unroll
        for (int b = 0; b < 4; b++)
#pragma unroll
            for (int e = 0; e < 4; e++) d[a][b][e] = 0.f;

    load_stage(smem + 0 * STG, i0, j0, 0,  tid); CP_COMMIT();
    load_stage(smem + 1 * STG, i0, j0, 64, tid); CP_COMMIT();

#pragma unroll 1
    for (int c = 0; c < 8; c++) {
        if (c >= 6) asm volatile("cp.async.wait_group 0;" ::: "memory");
        else        asm volatile("cp.async.wait_group 1;" ::: "memory");
        __syncthreads();
        if (c + 2 < 8) {
            load_stage(smem + ((c + 2) % 3) * STG, i0, j0, (c + 2) * 64, tid);
            CP_COMMIT();
        }
        const uint32_t As = smem + (c % 3) * STG;
        const uint32_t Bs = As + 16384;
#pragma unroll
        for (int ks = 0; ks < 4; ks++) {
            uint32_t a[4][4];
#pragma unroll
            for (int mt = 0; mt < 4; mt++) {
                int arow = wr * 64 + mt * 16 + (lane & 15);
                uint32_t ad = As + arow * 128 +
                              ((((ks << 1) | (lane >> 4)) ^ (arow & 7)) << 4);
                LDMATRIX_X4(a[mt], ad);
            }
#pragma unroll
            for (int np = 0; np < 2; np++) {
                int brow = wc * 32 + np * 16 + (lane & 15);
                uint32_t bd = Bs + brow * 128 +
                              ((((ks << 1) | (lane >> 4)) ^ (brow & 7)) << 4);
                uint32_t b[4];
                LDMATRIX_X4(b, bd);
#pragma unroll
                for (int mt = 0; mt < 4; mt++) {
                    MMA16816(d[mt][2 * np],     a[mt], b[0], b[2]);
                    MMA16816(d[mt][2 * np + 1], a[mt], b[1], b[3]);
                }
            }
        }
    }

    // epilogue: m = q_j - 2*gram; masked hardest pos/neg per row
#pragma unroll
    for (int mt = 0; mt < 4; mt++) {
        int r0 = wr * 64 + mt * 16 + (lane >> 2);
        int li0 = s_labi[r0], li1 = s_labi[r0 + 8];
        float hp0 = -BIGV, hp1 = -BIGV, hn0 = BIGV, hn1 = BIGV;
#pragma unroll
        for (int nt = 0; nt < 4; nt++) {
            int c0 = wc * 32 + nt * 8 + ((lane & 3) << 1);
            float q0 = s_qj[c0], q1 = s_qj[c0 + 1];
            int lj0 = s_labj[c0], lj1 = s_labj[c0 + 1];
            float m00 = fmaf(d[mt][nt][0], -2.f, q0);
            float m01 = fmaf(d[mt][nt][1], -2.f, q1);
            float m10 = fmaf(d[mt][nt][2], -2.f, q0);
            float m11 = fmaf(d[mt][nt][3], -2.f, q1);
            if (li0 == lj0) hp0 = fmaxf(hp0, m00); else hn0 = fminf(hn0, m00);
            if (li0 == lj1) hp0 = fmaxf(hp0, m01); else hn0 = fminf(hn0, m01);
            if (li1 == lj0) hp1 = fmaxf(hp1, m10); else hn1 = fminf(hn1, m10);
            if (li1 == lj1) hp1 = fmaxf(hp1, m11); else hn1 = fminf(hn1, m11);
        }
#pragma unroll
        for (int off = 1; off < 4; off <<= 1) {
            hp0 = fmaxf(hp0, __shfl_xor_sync(0xffffffffu, hp0, off));
            hp1 = fmaxf(hp1, __shfl_xor_sync(0xffffffffu, hp1, off));
            hn0 = fminf(hn0, __shfl_xor_sync(0xffffffffu, hn0, off));
            hn1 = fminf(hn1, __shfl_xor_sync(0xffffffffu, hn1, off));
        }
        if ((lane & 3) == 0) {
            hp_s[r0][wc] = hp0; hp_s[r0 + 8][wc] = hp1;
            hn_s[r0][wc] = hn0; hn_s[r0 + 8][wc] = hn1;
        }
    }
    __syncthreads();
    if (tid < 128) {
        float hp = fmaxf(fmaxf(hp_s[tid][0], hp_s[tid][1]),
                         fmaxf(hp_s[tid][2], hp_s[tid][3]));
        float hn = fminf(fminf(hn_s[tid][0], hn_s[tid][1]),
                         fminf(hn_s[tid][2], hn_s[tid][3]));
        g_hp[blockIdx.y][i0 + tid] = hp;
        g_hn[blockIdx.y][i0 + tid] = hn;
    }
}

// ---------------------------------------------------------------------------
// Kernel 3: parallel combine — 16 blocks, 1 thread per anchor.
// ---------------------------------------------------------------------------
__global__ void combine_kernel(const int* __restrict__ lab) {
    __shared__ int   cnt[512];
    __shared__ float ssum[256], scnt[256];
    const int tid = threadIdx.x;
    for (int i = tid; i < 512; i += 256) cnt[i] = 0;
    __syncthreads();
    for (int i = tid; i < B_SZ; i += 256) atomicAdd(&cnt[lab[i]], 1);
    __syncthreads();

    const int row = blockIdx.x * 256 + tid;
    float hp = -BIGV, hn = BIGV;
#pragma unroll
    for (int s = 0; s < NSPLIT; s++) {
        hp = fmaxf(hp, g_hp[s][row]);
        hn = fminf(hn, g_hn[s][row]);
    }
    int k = cnt[lab[row]];
    bool valid = (k >= 2) && (k < B_SZ);
    float p = g_p[row];
    float dp = sqrtf(fmaxf(p + hp, 0.f));
    float dn = sqrtf(fmaxf(p + hn, 0.f));
    float v = dp - dn + MARGIN;
    ssum[tid] = valid ? ((v > 0.f) ? v : 0.f) : 0.f;
    scnt[tid] = valid ? 1.f : 0.f;
    __syncthreads();
    for (int off = 128; off > 0; off >>= 1) {
        if (tid < off) { ssum[tid] += ssum[tid + off]; scnt[tid] += scnt[tid + off]; }
        __syncthreads();
    }
    if (tid == 0) { g_psum[blockIdx.x] = ssum[0]; g_pcnt[blockIdx.x] = scnt[0]; }
}

// ---------------------------------------------------------------------------
// Kernel 4: final scalar reduce.
// ---------------------------------------------------------------------------
__global__ void final_kernel(float* __restrict__ out) {
    const int tid = threadIdx.x;        // 32 threads
    float s = (tid < CBLKS) ? g_psum[tid] : 0.f;
    float c = (tid < CBLKS) ? g_pcnt[tid] : 0.f;
#pragma unroll
    for (int off = 16; off > 0; off >>= 1) {
        s += __shfl_xor_sync(0xffffffffu, s, off);
        c += __shfl_xor_sync(0xffffffffu, c, off);
    }
    if (tid == 0) out[0] = (c > 0.f) ? (s / c) : 0.f;
}

// ---------------------------------------------------------------------------
extern "C" void kernel_launch(void* const* d_in, const int* in_sizes, int n_in,
                              void* d_out, int out_size) {
    const float* E   = (const float*)d_in[0];
    const int*   lab = (const int*)d_in[1];
    float*       out = (float*)d_out;
    (void)in_sizes; (void)n_in; (void)out_size;

    cudaFuncSetAttribute(gemm_triplet_kernel,
                         cudaFuncAttributeMaxDynamicSharedMemorySize, DYN_SMEM);

    prep_stats_kernel<<<B_SZ / 8, 256>>>(E);
    gemm_triplet_kernel<<<dim3(B_SZ / 128, B_SZ / 128), 256, DYN_SMEM>>>(lab);
    combine_kernel<<<CBLKS, 256>>>(lab);
    final_kernel<<<1, 32>>>(out);
}

// round 6
// speedup vs baseline: 13.9299x; 1.3807x over previous
#include <cuda_runtime.h>
#include <cuda_fp16.h>
#include <cstdint>

#define B_SZ   4096
#define D_SZ   512
#define MARGIN 0.5f
#define EPSV   1e-6f
#define BIGV   1e9f

#define NSPLIT (B_SZ / 128)       // 32 tile rows/cols
#define NTILES (NSPLIT * (NSPLIT + 1) / 2)   // 528 upper-triangle tiles
#define STG    32768              // bytes per pipeline stage (A 16K + B 16K)
#define DYN_SMEM (3 * STG)
#define CBLKS  16                 // combine blocks (4096 / 256)

// ---------------- device scratch (no cudaMalloc allowed) ----------------
__device__ __half Ehalf[B_SZ * D_SZ];
__device__ float  g_q[B_SZ];   // sq - 2*eps*s
__device__ float  g_p[B_SZ];   // sq + 2*eps*s + D*eps^2
__device__ float  g_hp[NSPLIT][B_SZ];
__device__ float  g_hn[NSPLIT][B_SZ];
__device__ float  g_psum[CBLKS];
__device__ float  g_pcnt[CBLKS];

// ---------------- helpers ----------------
__device__ __forceinline__ uint32_t smem_u32(const void* p) {
    uint32_t a;
    asm("{ .reg .u64 t; cvta.to.shared.u64 t, %1; cvt.u32.u64 %0, t; }" : "=r"(a) : "l"(p));
    return a;
}

#define LDMATRIX_X4(r, addr)                                                      \
    asm volatile("ldmatrix.sync.aligned.m8n8.x4.shared.b16 {%0,%1,%2,%3}, [%4];"  \
        : "=r"((r)[0]), "=r"((r)[1]), "=r"((r)[2]), "=r"((r)[3]) : "r"(addr))

#define MMA16816(D, A, b0, b1)                                                    \
    asm volatile("mma.sync.aligned.m16n8k16.row.col.f32.f16.f16.f32 "             \
        "{%0,%1,%2,%3}, {%4,%5,%6,%7}, {%8,%9}, {%0,%1,%2,%3};"                   \
        : "+f"((D)[0]), "+f"((D)[1]), "+f"((D)[2]), "+f"((D)[3])                  \
        : "r"((A)[0]), "r"((A)[1]), "r"((A)[2]), "r"((A)[3]), "r"(b0), "r"(b1))

#define CP_ASYNC16(dst, src)                                                      \
    asm volatile("cp.async.cg.shared.global [%0], [%1], 16;"                      \
        :: "r"(dst), "l"(src) : "memory")
#define CP_COMMIT() asm volatile("cp.async.commit_group;" ::: "memory")

// load one 128x64-fp16 A tile (+ B tile unless diag) into a stage (xor swizzle)
__device__ __forceinline__ void load_stage(uint32_t base, int i0, int j0,
                                           int kc, int tid, bool diag) {
    uint32_t As = base, Bs = base + 16384;
#pragma unroll
    for (int it = 0; it < 4; it++) {
        int idx = tid + it * 256;
        int r = idx >> 3, ch = idx & 7;
        uint32_t dst = As + r * 128 + ((ch ^ (r & 7)) << 4);
        const void* src = &Ehalf[(size_t)(i0 + r) * D_SZ + kc + ch * 8];
        CP_ASYNC16(dst, src);
    }
    if (!diag) {
#pragma unroll
        for (int it = 0; it < 4; it++) {
            int idx = tid + it * 256;
            int r = idx >> 3, ch = idx & 7;
            uint32_t dst = Bs + r * 128 + ((ch ^ (r & 7)) << 4);
            const void* src = &Ehalf[(size_t)(j0 + r) * D_SZ + kc + ch * 8];
            CP_ASYNC16(dst, src);
        }
    }
}

// ---------------------------------------------------------------------------
// Kernel 1: fused fp32->fp16 convert + per-row stats. One warp per row.
// ---------------------------------------------------------------------------
__global__ void prep_stats_kernel(const float* __restrict__ E) {
    int warp = (blockIdx.x * blockDim.x + threadIdx.x) >> 5;
    int lane = threadIdx.x & 31;
    const float4* row = reinterpret_cast<const float4*>(E + (size_t)warp * D_SZ);
    uint2* hout = reinterpret_cast<uint2*>(Ehalf + (size_t)warp * D_SZ);
    float s = 0.f, sq = 0.f;
#pragma unroll
    for (int q = 0; q < 4; q++) {
        float4 v = row[lane + 32 * q];
        s  += v.x + v.y + v.z + v.w;
        sq += v.x * v.x + v.y * v.y + v.z * v.z + v.w * v.w;
        __half2 h0 = __floats2half2_rn(v.x, v.y);
        __half2 h1 = __floats2half2_rn(v.z, v.w);
        uint2 packed;
        packed.x = *reinterpret_cast<uint32_t*>(&h0);
        packed.y = *reinterpret_cast<uint32_t*>(&h1);
        hout[lane + 32 * q] = packed;
    }
#pragma unroll
    for (int off = 16; off > 0; off >>= 1) {
        s  += __shfl_xor_sync(0xffffffffu, s,  off);
        sq += __shfl_xor_sync(0xffffffffu, sq, off);
    }
    if (lane == 0) {
        g_q[warp] = sq - 2.f * EPSV * s;
        g_p[warp] = sq + 2.f * EPSV * s + (float)D_SZ * EPSV * EPSV;
    }
}

// ---------------------------------------------------------------------------
// Kernel 2: upper-triangle 128x128x512 fp16 gram tile, dual-sided epilogue.
// ---------------------------------------------------------------------------
__global__ void __launch_bounds__(256, 2)
gemm_triplet_kernel(const int* __restrict__ lab) {
    extern __shared__ __align__(1024) char dsm[];
    __shared__ int   s_labi[128];
    __shared__ int   s_labj[128];
    __shared__ float s_qi[128];
    __shared__ float s_qj[128];
    __shared__ float hp_s[128][4];
    __shared__ float hn_s[128][4];
    __shared__ float hp_cs[128][2];
    __shared__ float hn_cs[128][2];

    // map linear block id -> upper-triangle (ti, tj), ti <= tj
    int bid = blockIdx.x;
    int ti = 0, rem = bid;
    while (rem >= NSPLIT - ti) { rem -= NSPLIT - ti; ti++; }
    const int tj = ti + rem;
    const bool diag = (ti == tj);

    const int tid  = threadIdx.x;
    const int wid  = tid >> 5, lane = tid & 31;
    const int wr   = wid >> 2, wc = wid & 3;        // 2 x 4 warp grid
    const int i0   = ti * 128;
    const int j0   = tj * 128;
    const uint32_t smem = smem_u32(dsm);

    if (tid < 128) {
        s_labi[tid] = lab[i0 + tid];
        s_labj[tid] = lab[j0 + tid];
        s_qi[tid]   = g_q[i0 + tid];
        s_qj[tid]   = g_q[j0 + tid];
    }

    float d[4][4][4];
#pragma unroll
    for (int a = 0; a < 4; a++)
#pragma unroll
        for (int b = 0; b < 4; b++)
#pragma unroll
            for (int e = 0; e < 4; e++) d[a][b][e] = 0.f;

    load_stage(smem + 0 * STG, i0, j0, 0,  tid, diag); CP_COMMIT();
    load_stage(smem + 1 * STG, i0, j0, 64, tid, diag); CP_COMMIT();

#pragma unroll 1
    for (int c = 0; c < 8; c++) {
        if (c >= 6) asm volatile("cp.async.wait_group 0;" ::: "memory");
        else        asm volatile("cp.async.wait_group 1;" ::: "memory");
        __syncthreads();
        if (c + 2 < 8) {
            load_stage(smem + ((c + 2) % 3) * STG, i0, j0, (c + 2) * 64, tid, diag);
            CP_COMMIT();
        }
        const uint32_t As = smem + (c % 3) * STG;
        const uint32_t Bs = diag ? As : (As + 16384);
#pragma unroll
        for (int ks = 0; ks < 4; ks++) {
            uint32_t a[4][4];
#pragma unroll
            for (int mt = 0; mt < 4; mt++) {
                int arow = wr * 64 + mt * 16 + (lane & 15);
                uint32_t ad = As + arow * 128 +
                              ((((ks << 1) | (lane >> 4)) ^ (arow & 7)) << 4);
                LDMATRIX_X4(a[mt], ad);
            }
#pragma unroll
            for (int np = 0; np < 2; np++) {
                int brow = wc * 32 + np * 16 + (lane & 15);
                uint32_t bd = Bs + brow * 128 +
                              ((((ks << 1) | (lane >> 4)) ^ (brow & 7)) << 4);
                uint32_t b[4];
                LDMATRIX_X4(b, bd);
#pragma unroll
                for (int mt = 0; mt < 4; mt++) {
                    MMA16816(d[mt][2 * np],     a[mt], b[0], b[2]);
                    MMA16816(d[mt][2 * np + 1], a[mt], b[1], b[3]);
                }
            }
        }
    }

    // dual-sided epilogue
    float hpc[8], hnc[8];
#pragma unroll
    for (int k = 0; k < 8; k++) { hpc[k] = -BIGV; hnc[k] = BIGV; }

#pragma unroll
    for (int mt = 0; mt < 4; mt++) {
        int r0 = wr * 64 + mt * 16 + (lane >> 2);
        int li0 = s_labi[r0], li1 = s_labi[r0 + 8];
        float qi0 = s_qi[r0], qi1 = s_qi[r0 + 8];
        float hp0 = -BIGV, hp1 = -BIGV, hn0 = BIGV, hn1 = BIGV;
#pragma unroll
        for (int nt = 0; nt < 4; nt++) {
            int c0 = wc * 32 + nt * 8 + ((lane & 3) << 1);
            float q0 = s_qj[c0], q1 = s_qj[c0 + 1];
            int lj0 = s_labj[c0], lj1 = s_labj[c0 + 1];
            float g00 = d[mt][nt][0], g01 = d[mt][nt][1];
            float g10 = d[mt][nt][2], g11 = d[mt][nt][3];
            bool e00 = (li0 == lj0), e01 = (li0 == lj1);
            bool e10 = (li1 == lj0), e11 = (li1 == lj1);
            // row-side: anchor = row r (ti block), split tj
            float m00 = fmaf(g00, -2.f, q0);
            float m01 = fmaf(g01, -2.f, q1);
            float m10 = fmaf(g10, -2.f, q0);
            float m11 = fmaf(g11, -2.f, q1);
            if (e00) hp0 = fmaxf(hp0, m00); else hn0 = fminf(hn0, m00);
            if (e01) hp0 = fmaxf(hp0, m01); else hn0 = fminf(hn0, m01);
            if (e10) hp1 = fmaxf(hp1, m10); else hn1 = fminf(hn1, m10);
            if (e11) hp1 = fmaxf(hp1, m11); else hn1 = fminf(hn1, m11);
            if (!diag) {
                // col-side: anchor = col c (tj block), split ti
                float n00 = fmaf(g00, -2.f, qi0);
                float n01 = fmaf(g01, -2.f, qi0);
                float n10 = fmaf(g10, -2.f, qi1);
                float n11 = fmaf(g11, -2.f, qi1);
                int k0 = nt * 2, k1 = nt * 2 + 1;
                if (e00) hpc[k0] = fmaxf(hpc[k0], n00); else hnc[k0] = fminf(hnc[k0], n00);
                if (e10) hpc[k0] = fmaxf(hpc[k0], n10); else hnc[k0] = fminf(hnc[k0], n10);
                if (e01) hpc[k1] = fmaxf(hpc[k1], n01); else hnc[k1] = fminf(hnc[k1], n01);
                if (e11) hpc[k1] = fmaxf(hpc[k1], n11); else hnc[k1] = fminf(hnc[k1], n11);
            }
        }
        // row-side reduce across 4 col-lanes
#pragma unroll
        for (int off = 1; off < 4; off <<= 1) {
            hp0 = fmaxf(hp0, __shfl_xor_sync(0xffffffffu, hp0, off));
            hp1 = fmaxf(hp1, __shfl_xor_sync(0xffffffffu, hp1, off));
            hn0 = fminf(hn0, __shfl_xor_sync(0xffffffffu, hn0, off));
            hn1 = fminf(hn1, __shfl_xor_sync(0xffffffffu, hn1, off));
        }
        if ((lane & 3) == 0) {
            hp_s[r0][wc] = hp0; hp_s[r0 + 8][wc] = hp1;
            hn_s[r0][wc] = hn0; hn_s[r0 + 8][wc] = hn1;
        }
    }

    if (!diag) {
        // col-side reduce across 8 row-lanes (shfl offsets 4, 8, 16)
#pragma unroll
        for (int off = 4; off <= 16; off <<= 1) {
#pragma unroll
            for (int k = 0; k < 8; k++) {
                hpc[k] = fmaxf(hpc[k], __shfl_xor_sync(0xffffffffu, hpc[k], off));
                hnc[k] = fminf(hnc[k], __shfl_xor_sync(0xffffffffu, hnc[k], off));
            }
        }
        if ((lane >> 2) == 0) {
#pragma unroll
            for (int k = 0; k < 8; k++) {
                int col = wc * 32 + (k >> 1) * 8 + ((lane & 3) << 1) + (k & 1);
                hp_cs[col][wr] = hpc[k];
                hn_cs[col][wr] = hnc[k];
            }
        }
    }
    __syncthreads();
    if (tid < 128) {
        float hp = fmaxf(fmaxf(hp_s[tid][0], hp_s[tid][1]),
                         fmaxf(hp_s[tid][2], hp_s[tid][3]));
        float hn = fminf(fminf(hn_s[tid][0], hn_s[tid][1]),
                         fminf(hn_s[tid][2], hn_s[tid][3]));
        g_hp[tj][i0 + tid] = hp;
        g_hn[tj][i0 + tid] = hn;
        if (!diag) {
            float hpc2 = fmaxf(hp_cs[tid][0], hp_cs[tid][1]);
            float hnc2 = fminf(hn_cs[tid][0], hn_cs[tid][1]);
            g_hp[ti][j0 + tid] = hpc2;
            g_hn[ti][j0 + tid] = hnc2;
        }
    }
}

// ---------------------------------------------------------------------------
// Kernel 3: parallel combine — 16 blocks, 1 thread per anchor.
// ---------------------------------------------------------------------------
__global__ void combine_kernel(const int* __restrict__ lab) {
    __shared__ int   cnt[512];
    __shared__ float ssum[256], scnt[256];
    const int tid = threadIdx.x;
    for (int i = tid; i < 512; i += 256) cnt[i] = 0;
    __syncthreads();
    for (int i = tid; i < B_SZ; i += 256) atomicAdd(&cnt[lab[i]], 1);
    __syncthreads();

    const int row = blockIdx.x * 256 + tid;
    float hp = -BIGV, hn = BIGV;
#pragma unroll
    for (int s = 0; s < NSPLIT; s++) {
        hp = fmaxf(hp, g_hp[s][row]);
        hn = fminf(hn, g_hn[s][row]);
    }
    int k = cnt[lab[row]];
    bool valid = (k >= 2) && (k < B_SZ);
    float p = g_p[row];
    float dp = sqrtf(fmaxf(p + hp, 0.f));
    float dn = sqrtf(fmaxf(p + hn, 0.f));
    float v = dp - dn + MARGIN;
    ssum[tid] = valid ? ((v > 0.f) ? v : 0.f) : 0.f;
    scnt[tid] = valid ? 1.f : 0.f;
    __syncthreads();
    for (int off = 128; off > 0; off >>= 1) {
        if (tid < off) { ssum[tid] += ssum[tid + off]; scnt[tid] += scnt[tid + off]; }
        __syncthreads();
    }
    if (tid == 0) { g_psum[blockIdx.x] = ssum[0]; g_pcnt[blockIdx.x] = scnt[0]; }
}

// ---------------------------------------------------------------------------
// Kernel 4: final scalar reduce.
// ---------------------------------------------------------------------------
__global__ void final_kernel(float* __restrict__ out) {
    const int tid = threadIdx.x;        // 32 threads
    float s = (tid < CBLKS) ? g_psum[tid] : 0.f;
    float c = (tid < CBLKS) ? g_pcnt[tid] : 0.f;
#pragma unroll
    for (int off = 16; off > 0; off >>= 1) {
        s += __shfl_xor_sync(0xffffffffu, s, off);
        c += __shfl_xor_sync(0xffffffffu, c, off);
    }
    if (tid == 0) out[0] = (c > 0.f) ? (s / c) : 0.f;
}

// ---------------------------------------------------------------------------
extern "C" void kernel_launch(void* const* d_in, const int* in_sizes, int n_in,
                              void* d_out, int out_size) {
    const float* E   = (const float*)d_in[0];
    const int*   lab = (const int*)d_in[1];
    float*       out = (float*)d_out;
    (void)in_sizes; (void)n_in; (void)out_size;

    cudaFuncSetAttribute(gemm_triplet_kernel,
                         cudaFuncAttributeMaxDynamicSharedMemorySize, DYN_SMEM);

    prep_stats_kernel<<<B_SZ / 8, 256>>>(E);
    gemm_triplet_kernel<<<NTILES, 256, DYN_SMEM>>>(lab);
    combine_kernel<<<CBLKS, 256>>>(lab);
    final_kernel<<<1, 32>>>(out);
}